// round 1
// baseline (speedup 1.0000x reference)
#include <cuda_runtime.h>
#include <math.h>

#define T_VOCAB 50265
#define CTX     384
#define BS      4
#define NDS     2048

// padded vocab to multiple of 4 for vectorized smem zeroing
#define T_PAD   50268
#define SMEM_BYTES (T_PAD * 4)

// scratch (allocation-free rule: __device__ globals)
__device__ int   g_mc[BS * NDS];
__device__ float g_w [BS * NDS];

// ---------------------------------------------------------------------------
// Kernel A: match counts. One warp per dataset row n; input rows in smem.
// ---------------------------------------------------------------------------
__global__ void mc_kernel(const int* __restrict__ input,
                          const int* __restrict__ dataset) {
    __shared__ int s_in[BS * CTX];
    int tid = threadIdx.x;
    for (int i = tid; i < BS * CTX; i += blockDim.x) s_in[i] = input[i];
    __syncthreads();

    int warp = tid >> 5, lane = tid & 31;
    int n = blockIdx.x * (blockDim.x >> 5) + warp;
    if (n >= NDS) return;

    int cnt0 = 0, cnt1 = 0, cnt2 = 0, cnt3 = 0;
    const int* row = dataset + n * CTX;
    for (int s = lane; s < CTX; s += 32) {
        int dv = row[s];
        cnt0 += (dv == s_in[0 * CTX + s]);
        cnt1 += (dv == s_in[1 * CTX + s]);
        cnt2 += (dv == s_in[2 * CTX + s]);
        cnt3 += (dv == s_in[3 * CTX + s]);
    }
    #pragma unroll
    for (int off = 16; off > 0; off >>= 1) {
        cnt0 += __shfl_down_sync(0xffffffffu, cnt0, off);
        cnt1 += __shfl_down_sync(0xffffffffu, cnt1, off);
        cnt2 += __shfl_down_sync(0xffffffffu, cnt2, off);
        cnt3 += __shfl_down_sync(0xffffffffu, cnt3, off);
    }
    if (lane == 0) {
        g_mc[0 * NDS + n] = cnt0;
        g_mc[1 * NDS + n] = cnt1;
        g_mc[2 * NDS + n] = cnt2;
        g_mc[3 * NDS + n] = cnt3;
    }
}

// ---------------------------------------------------------------------------
// Kernel B: softmax over the dataset axis per batch element.
// logp differences depend only on mc * d, d = log(1 + t*V/(1-t)).
// ---------------------------------------------------------------------------
__global__ void softmax_kernel(const float* __restrict__ t) {
    const int b   = blockIdx.x;
    const int tid = threadIdx.x;
    const float tb = t[b];
    // d = log_a - log_b = log( (t + (1-t)/V) / ((1-t)/V) ) = log(1 + t*V/(1-t))
    const float d = logf(1.0f + tb * (float)T_VOCAB / (1.0f - tb));

    __shared__ int   s_max[256];
    __shared__ float s_sum[256];

    int mymax = -1;
    for (int n = tid; n < NDS; n += 256) mymax = max(mymax, g_mc[b * NDS + n]);
    s_max[tid] = mymax;
    __syncthreads();
    for (int off = 128; off > 0; off >>= 1) {
        if (tid < off) s_max[tid] = max(s_max[tid], s_max[tid + off]);
        __syncthreads();
    }
    const int mcmax = s_max[0];

    float mysum = 0.0f;
    for (int n = tid; n < NDS; n += 256) {
        float e = expf((float)(g_mc[b * NDS + n] - mcmax) * d);
        g_w[b * NDS + n] = e;
        mysum += e;
    }
    s_sum[tid] = mysum;
    __syncthreads();
    for (int off = 128; off > 0; off >>= 1) {
        if (tid < off) s_sum[tid] += s_sum[tid + off];
        __syncthreads();
    }
    const float inv = 1.0f / s_sum[0];
    __syncthreads();
    for (int n = tid; n < NDS; n += 256) g_w[b * NDS + n] *= inv;
}

// ---------------------------------------------------------------------------
// Kernel C: per-(b,s) vocab row accumulated in 201 KB shared memory, then
// streamed to GMEM with STG.128. One CTA per (s, b); occ = 1 CTA/SM.
// ---------------------------------------------------------------------------
extern __shared__ float sm[];

__global__ __launch_bounds__(1024, 1)
void scatter_kernel(const int* __restrict__ dataset, float* __restrict__ out) {
    const int s   = blockIdx.x;
    const int b   = blockIdx.y;
    const int tid = threadIdx.x;

    // zero the row (vectorized STS.128)
    float4* sm4 = reinterpret_cast<float4*>(sm);
    const float4 z = make_float4(0.f, 0.f, 0.f, 0.f);
    #pragma unroll
    for (int i = tid; i < T_PAD / 4; i += 1024) sm4[i] = z;
    __syncthreads();

    // accumulate: 2048 shared atomics, collisions rare (random tokens of 50265)
    #pragma unroll
    for (int n = tid; n < NDS; n += 1024) {
        int tok = dataset[n * CTX + s];
        atomicAdd(&sm[tok], g_w[b * NDS + n]);
    }
    __syncthreads();

    // stream out; row base offset is odd (V % 4 == 1), so peel head/tail
    const size_t base = ((size_t)b * CTX + (size_t)s) * (size_t)T_VOCAB;
    float* orow = out + base;
    const int mis  = (int)(base & 3);
    const int head = mis ? (4 - mis) : 0;

    if (tid < head) orow[tid] = sm[tid];

    const int vend = head + ((T_VOCAB - head) & ~3);
    for (int v = head + tid * 4; v < vend; v += 4096) {
        float4 val;
        val.x = sm[v + 0];
        val.y = sm[v + 1];
        val.z = sm[v + 2];
        val.w = sm[v + 3];
        *reinterpret_cast<float4*>(orow + v) = val;
    }
    for (int v = vend + tid; v < T_VOCAB; v += 1024) orow[v] = sm[v];
}

// ---------------------------------------------------------------------------
extern "C" void kernel_launch(void* const* d_in, const int* in_sizes, int n_in,
                              void* d_out, int out_size) {
    const int*   input   = (const int*)d_in[0];    // (4, 384)
    const int*   dataset = (const int*)d_in[1];    // (2048, 384)
    const float* t       = (const float*)d_in[2];  // (4,)
    float* out = (float*)d_out;                    // (4, 384, 50265)

    // idempotent; allows 201 KB dynamic smem
    cudaFuncSetAttribute(scatter_kernel,
                         cudaFuncAttributeMaxDynamicSharedMemorySize, SMEM_BYTES);

    // A: 8 warps/block, 1 warp per dataset row -> 256 blocks
    mc_kernel<<<NDS / 8, 256>>>(input, dataset);

    // B: one block per batch element
    softmax_kernel<<<BS, 256>>>(t);

    // C: one CTA per (position, batch)
    dim3 grid(CTX, BS);
    scatter_kernel<<<grid, 1024, SMEM_BYTES>>>(dataset, out);
}

// round 2
// speedup vs baseline: 1.0414x; 1.0414x over previous
#include <cuda_runtime.h>
#include <math.h>

#define T_VOCAB 50265
#define CTX     384
#define BS      4
#define NDS     2048

// scratch (allocation-free rule: __device__ globals)
__device__ int   g_mc[BS * NDS];
__device__ float g_w [BS * NDS];
__device__ int   g_dt[CTX * NDS];   // transposed dataset: g_dt[s*NDS + n]

// ---------------------------------------------------------------------------
// Kernel T: tiled transpose dataset (n,s) -> g_dt (s,n) so the scatter kernel
// reads token columns coalesced.
// ---------------------------------------------------------------------------
__global__ void transpose_kernel(const int* __restrict__ dataset) {
    __shared__ int tile[32][33];
    const int n0 = blockIdx.x * 32;   // 2048/32 = 64
    const int s0 = blockIdx.y * 32;   // 384/32  = 12
    const int tx = threadIdx.x, ty = threadIdx.y;  // 32 x 8
    #pragma unroll
    for (int i = 0; i < 32; i += 8)
        tile[ty + i][tx] = dataset[(n0 + ty + i) * CTX + s0 + tx];
    __syncthreads();
    #pragma unroll
    for (int i = 0; i < 32; i += 8)
        g_dt[(s0 + ty + i) * NDS + n0 + tx] = tile[tx][ty + i];
}

// ---------------------------------------------------------------------------
// Kernel A: match counts. One warp per dataset row n; vectorized int4 loads.
// ---------------------------------------------------------------------------
__global__ void mc_kernel(const int* __restrict__ input,
                          const int* __restrict__ dataset) {
    __shared__ int4 s_in[BS][CTX / 4];    // 4 x 96 int4
    const int tid = threadIdx.x;
    for (int i = tid; i < BS * CTX / 4; i += blockDim.x)
        (&s_in[0][0])[i] = ((const int4*)input)[i];
    __syncthreads();

    const int warp = tid >> 5, lane = tid & 31;
    const int n = blockIdx.x * (blockDim.x >> 5) + warp;
    const int4* row = (const int4*)(dataset + n * CTX);

    int c0 = 0, c1 = 0, c2 = 0, c3 = 0;
    #pragma unroll
    for (int i = 0; i < 3; i++) {               // 3 * 32 lanes * 4 = 384
        const int idx = lane + 32 * i;
        const int4 dv = row[idx];
        int4 a;
        a = s_in[0][idx];
        c0 += (dv.x == a.x) + (dv.y == a.y) + (dv.z == a.z) + (dv.w == a.w);
        a = s_in[1][idx];
        c1 += (dv.x == a.x) + (dv.y == a.y) + (dv.z == a.z) + (dv.w == a.w);
        a = s_in[2][idx];
        c2 += (dv.x == a.x) + (dv.y == a.y) + (dv.z == a.z) + (dv.w == a.w);
        a = s_in[3][idx];
        c3 += (dv.x == a.x) + (dv.y == a.y) + (dv.z == a.z) + (dv.w == a.w);
    }
    #pragma unroll
    for (int off = 16; off > 0; off >>= 1) {
        c0 += __shfl_down_sync(0xffffffffu, c0, off);
        c1 += __shfl_down_sync(0xffffffffu, c1, off);
        c2 += __shfl_down_sync(0xffffffffu, c2, off);
        c3 += __shfl_down_sync(0xffffffffu, c3, off);
    }
    if (lane == 0) {
        g_mc[0 * NDS + n] = c0;
        g_mc[1 * NDS + n] = c1;
        g_mc[2 * NDS + n] = c2;
        g_mc[3 * NDS + n] = c3;
    }
}

// ---------------------------------------------------------------------------
// Kernel B: softmax over the dataset axis per batch element.
// softmax(logp) depends only on mc * d, d = log(1 + t*V/(1-t)).
// ---------------------------------------------------------------------------
__global__ void softmax_kernel(const float* __restrict__ t) {
    const int b   = blockIdx.x;
    const int tid = threadIdx.x;
    const float tb = t[b];
    const float d = logf(1.0f + tb * (float)T_VOCAB / (1.0f - tb));

    __shared__ int   s_max[256];
    __shared__ float s_sum[256];

    int mymax = -1;
    for (int n = tid; n < NDS; n += 256) mymax = max(mymax, g_mc[b * NDS + n]);
    s_max[tid] = mymax;
    __syncthreads();
    for (int off = 128; off > 0; off >>= 1) {
        if (tid < off) s_max[tid] = max(s_max[tid], s_max[tid + off]);
        __syncthreads();
    }
    const int mcmax = s_max[0];

    float mysum = 0.0f;
    for (int n = tid; n < NDS; n += 256) {
        float e = expf((float)(g_mc[b * NDS + n] - mcmax) * d);
        g_w[b * NDS + n] = e;
        mysum += e;
    }
    s_sum[tid] = mysum;
    __syncthreads();
    for (int off = 128; off > 0; off >>= 1) {
        if (tid < off) s_sum[tid] += s_sum[tid + off];
        __syncthreads();
    }
    const float inv = 1.0f / s_sum[0];
    __syncthreads();
    for (int n = tid; n < NDS; n += 256) g_w[b * NDS + n] *= inv;
}

// ---------------------------------------------------------------------------
// Kernel C: per-(b,s) row. Phase 1 streams zeros straight to GMEM (STG.128,
// full-line writes). Phase 2 does 2048 global atomicAdds (RED) into the
// freshly-written, L2-resident row. No shared memory -> 4 CTAs/SM, phases of
// different CTAs overlap and keep the store pipe / DRAM saturated.
// ---------------------------------------------------------------------------
__global__ __launch_bounds__(512)
void scatter_kernel(float* __restrict__ out) {
    const int s   = blockIdx.x;
    const int b   = blockIdx.y;
    const int tid = threadIdx.x;

    const size_t base = ((size_t)b * CTX + (size_t)s) * (size_t)T_VOCAB;
    float* orow = out + base;

    // ---- phase 1: zero the row (vectorized, head/tail peeled) ----
    const int mis  = (int)(base & 3);
    const int head = (4 - mis) & 3;
    if (tid < head) orow[tid] = 0.0f;

    const int vend = head + ((T_VOCAB - head) & ~3);
    const float4 z = make_float4(0.f, 0.f, 0.f, 0.f);
    for (int v = head + tid * 4; v < vend; v += 512 * 4)
        *reinterpret_cast<float4*>(orow + v) = z;
    for (int v = vend + tid; v < T_VOCAB; v += 512) orow[v] = 0.0f;

    __threadfence();     // order zero-stores before the atomics below
    __syncthreads();

    // ---- phase 2: scatter-add the 2048 weighted tokens (L2 hits) ----
    const int*   col = g_dt + s * NDS;     // coalesced (transposed)
    const float* w   = g_w  + b * NDS;
    #pragma unroll 4
    for (int n = tid; n < NDS; n += 512)
        atomicAdd(orow + col[n], w[n]);    // no return value -> RED.E.ADD
}

// ---------------------------------------------------------------------------
extern "C" void kernel_launch(void* const* d_in, const int* in_sizes, int n_in,
                              void* d_out, int out_size) {
    const int*   input   = (const int*)d_in[0];    // (4, 384)
    const int*   dataset = (const int*)d_in[1];    // (2048, 384)
    const float* t       = (const float*)d_in[2];  // (4,)
    float* out = (float*)d_out;                    // (4, 384, 50265) f32

    // T: transpose dataset for coalesced column reads in scatter
    dim3 tgrid(NDS / 32, CTX / 32);
    transpose_kernel<<<tgrid, dim3(32, 8)>>>(dataset);

    // A: 8 warps/block, 1 warp per dataset row -> 256 blocks
    mc_kernel<<<NDS / 8, 256>>>(input, dataset);

    // B: one block per batch element
    softmax_kernel<<<BS, 256>>>(t);

    // C: one CTA per (position, batch)
    dim3 grid(CTX, BS);
    scatter_kernel<<<grid, 512>>>(out);
}

// round 3
// speedup vs baseline: 1.2599x; 1.2098x over previous
#include <cuda_runtime.h>
#include <math.h>

#define T_VOCAB 50265
#define CTX     384
#define BS      4
#define NDS     2048

#define NQ      4                 // vocab quarters per row
#define QLEN    12567             // ceil(50265/4); last quarter is 12564
#define QPAD    12568             // padded to multiple of 4 floats
#define SMEM_BYTES (QPAD * 4)     // 50272 B -> 4 CTAs/SM

// scratch (allocation-free rule: __device__ globals)
__device__ int   g_mc[BS * NDS];
__device__ float g_w [BS * NDS];
__device__ int   g_dt[CTX * NDS];   // transposed dataset: g_dt[s*NDS + n]

// ---------------------------------------------------------------------------
// Kernel T: tiled transpose dataset (n,s) -> g_dt (s,n) so the scatter kernel
// reads token columns coalesced.
// ---------------------------------------------------------------------------
__global__ void transpose_kernel(const int* __restrict__ dataset) {
    __shared__ int tile[32][33];
    const int n0 = blockIdx.x * 32;   // 2048/32 = 64
    const int s0 = blockIdx.y * 32;   // 384/32  = 12
    const int tx = threadIdx.x, ty = threadIdx.y;  // 32 x 8
    #pragma unroll
    for (int i = 0; i < 32; i += 8)
        tile[ty + i][tx] = dataset[(n0 + ty + i) * CTX + s0 + tx];
    __syncthreads();
    #pragma unroll
    for (int i = 0; i < 32; i += 8)
        g_dt[(s0 + ty + i) * NDS + n0 + tx] = tile[tx][ty + i];
}

// ---------------------------------------------------------------------------
// Kernel A: match counts. One warp per dataset row n; vectorized int4 loads.
// ---------------------------------------------------------------------------
__global__ void mc_kernel(const int* __restrict__ input,
                          const int* __restrict__ dataset) {
    __shared__ int4 s_in[BS][CTX / 4];    // 4 x 96 int4
    const int tid = threadIdx.x;
    for (int i = tid; i < BS * CTX / 4; i += blockDim.x)
        (&s_in[0][0])[i] = ((const int4*)input)[i];
    __syncthreads();

    const int warp = tid >> 5, lane = tid & 31;
    const int n = blockIdx.x * (blockDim.x >> 5) + warp;
    const int4* row = (const int4*)(dataset + n * CTX);

    int c0 = 0, c1 = 0, c2 = 0, c3 = 0;
    #pragma unroll
    for (int i = 0; i < 3; i++) {               // 3 * 32 lanes * 4 = 384
        const int idx = lane + 32 * i;
        const int4 dv = row[idx];
        int4 a;
        a = s_in[0][idx];
        c0 += (dv.x == a.x) + (dv.y == a.y) + (dv.z == a.z) + (dv.w == a.w);
        a = s_in[1][idx];
        c1 += (dv.x == a.x) + (dv.y == a.y) + (dv.z == a.z) + (dv.w == a.w);
        a = s_in[2][idx];
        c2 += (dv.x == a.x) + (dv.y == a.y) + (dv.z == a.z) + (dv.w == a.w);
        a = s_in[3][idx];
        c3 += (dv.x == a.x) + (dv.y == a.y) + (dv.z == a.z) + (dv.w == a.w);
    }
    #pragma unroll
    for (int off = 16; off > 0; off >>= 1) {
        c0 += __shfl_down_sync(0xffffffffu, c0, off);
        c1 += __shfl_down_sync(0xffffffffu, c1, off);
        c2 += __shfl_down_sync(0xffffffffu, c2, off);
        c3 += __shfl_down_sync(0xffffffffu, c3, off);
    }
    if (lane == 0) {
        g_mc[0 * NDS + n] = c0;
        g_mc[1 * NDS + n] = c1;
        g_mc[2 * NDS + n] = c2;
        g_mc[3 * NDS + n] = c3;
    }
}

// ---------------------------------------------------------------------------
// Kernel B: softmax over the dataset axis per batch element.
// softmax(logp) depends only on mc * d, d = log(1 + t*V/(1-t)).
// ---------------------------------------------------------------------------
__global__ void softmax_kernel(const float* __restrict__ t) {
    const int b   = blockIdx.x;
    const int tid = threadIdx.x;
    const float tb = t[b];
    const float d = logf(1.0f + tb * (float)T_VOCAB / (1.0f - tb));

    __shared__ int   s_max[256];
    __shared__ float s_sum[256];

    int mymax = -1;
    for (int n = tid; n < NDS; n += 256) mymax = max(mymax, g_mc[b * NDS + n]);
    s_max[tid] = mymax;
    __syncthreads();
    for (int off = 128; off > 0; off >>= 1) {
        if (tid < off) s_max[tid] = max(s_max[tid], s_max[tid + off]);
        __syncthreads();
    }
    const int mcmax = s_max[0];

    float mysum = 0.0f;
    for (int n = tid; n < NDS; n += 256) {
        float e = expf((float)(g_mc[b * NDS + n] - mcmax) * d);
        g_w[b * NDS + n] = e;
        mysum += e;
    }
    s_sum[tid] = mysum;
    __syncthreads();
    for (int off = 128; off > 0; off >>= 1) {
        if (tid < off) s_sum[tid] += s_sum[tid + off];
        __syncthreads();
    }
    const float inv = 1.0f / s_sum[0];
    __syncthreads();
    for (int n = tid; n < NDS; n += 256) g_w[b * NDS + n] *= inv;
}

// ---------------------------------------------------------------------------
// Kernel C: one CTA per (s, b, vocab-quarter). The quarter row lives in a
// 50 KB smem slab (occ = 4 CTAs/SM). Zero slab -> scan the 2048-token column
// (coalesced via transpose, L2-shared by 16 CTAs) with a range filter and
// shared-memory atomics -> stream slab to GMEM with STG.128. Every output
// byte touches DRAM exactly once; no global atomics, no DRAM read-back.
// ---------------------------------------------------------------------------
extern __shared__ float sm[];

__global__ __launch_bounds__(512)
void scatter_kernel(float* __restrict__ out) {
    const int s   = blockIdx.x;
    const int b   = blockIdx.y;
    const int q   = blockIdx.z;
    const int tid = threadIdx.x;

    const int v0  = q * QLEN;
    const int len = min(QLEN, T_VOCAB - v0);

    // ---- zero the slab (STS.128) ----
    float4* sm4 = reinterpret_cast<float4*>(sm);
    const float4 z4 = make_float4(0.f, 0.f, 0.f, 0.f);
    #pragma unroll
    for (int i = tid; i < QPAD / 4; i += 512) sm4[i] = z4;
    __syncthreads();

    // ---- scan token column, range-filter, accumulate in smem ----
    const int*   col = g_dt + s * NDS;
    const float* w   = g_w  + b * NDS;
    #pragma unroll
    for (int n = tid; n < NDS; n += 512) {
        const int rel = col[n] - v0;
        if ((unsigned)rel < (unsigned)len)
            atomicAdd(&sm[rel], w[n]);
    }
    __syncthreads();

    // ---- stream slab out; peel for 16B alignment of the GMEM pointer ----
    const size_t base = ((size_t)b * CTX + (size_t)s) * (size_t)T_VOCAB + v0;
    float* orow = out + base;
    const int mis  = (int)(base & 3);
    const int head = (4 - mis) & 3;

    if (tid < head && tid < len) orow[tid] = sm[tid];

    const int vend = head + ((len - head) & ~3);
    for (int v = head + tid * 4; v < vend; v += 512 * 4) {
        float4 val;
        val.x = sm[v + 0];
        val.y = sm[v + 1];
        val.z = sm[v + 2];
        val.w = sm[v + 3];
        *reinterpret_cast<float4*>(orow + v) = val;
    }
    for (int v = vend + tid; v < len; v += 512) orow[v] = sm[v];
}

// ---------------------------------------------------------------------------
extern "C" void kernel_launch(void* const* d_in, const int* in_sizes, int n_in,
                              void* d_out, int out_size) {
    const int*   input   = (const int*)d_in[0];    // (4, 384)
    const int*   dataset = (const int*)d_in[1];    // (2048, 384)
    const float* t       = (const float*)d_in[2];  // (4,)
    float* out = (float*)d_out;                    // (4, 384, 50265) f32

    cudaFuncSetAttribute(scatter_kernel,
                         cudaFuncAttributeMaxDynamicSharedMemorySize, SMEM_BYTES);

    // T: transpose dataset for coalesced column reads in scatter
    dim3 tgrid(NDS / 32, CTX / 32);
    transpose_kernel<<<tgrid, dim3(32, 8)>>>(dataset);

    // A: 8 warps/block, 1 warp per dataset row -> 256 blocks
    mc_kernel<<<NDS / 8, 256>>>(input, dataset);

    // B: one block per batch element
    softmax_kernel<<<BS, 256>>>(t);

    // C: one CTA per (position, batch, vocab-quarter)
    dim3 grid(CTX, BS, NQ);
    scatter_kernel<<<grid, 512, SMEM_BYTES>>>(out);
}